// round 5
// baseline (speedup 1.0000x reference)
#include <cuda_runtime.h>
#include <cuda_fp16.h>
#include <math.h>
#include <stdint.h>

#define HDIM  1024
#define IDIM  2816
#define TWOI  5632
#define NEXP  8
#define NTOK  2048
#define NGRP  9   // 8 experts + base (group 8)

#define AS_STRIDE 20            // half2 (4B) units: 16 data + 4 pad -> conflict-free
#define BS_STRIDE 20
#define A_BUF (128 * AS_STRIDE) // uint32 words per A buffer
#define B_BUF (256 * BS_STRIDE) // uint32 words per B buffer
#define SMEM_BYTES ((2 * A_BUF + 2 * B_BUF) * 4)   // 61440

// ---------------- scratch (device globals; no allocation) ----------------
__device__ int    g_cnt[NGRP];
__device__ int    g_tok[NGRP * NTOK];
__device__ int    g_te[NTOK * 2];
__device__ int    g_tp[NTOK * 2];
__device__ float  g_tw[NTOK * 2];
__device__ __half g_act[(size_t)NGRP * NTOK * IDIM];
__device__ float  g_y  [(size_t)NGRP * NTOK * HDIM];

#define MMA_F16(C, A, B)                                                      \
    asm volatile(                                                             \
        "mma.sync.aligned.m16n8k16.row.col.f32.f16.f16.f32 "                  \
        "{%0,%1,%2,%3}, {%4,%5,%6,%7}, {%8,%9}, {%0,%1,%2,%3};"               \
        : "+f"((C)[0]), "+f"((C)[1]), "+f"((C)[2]), "+f"((C)[3])              \
        : "r"((A)[0]), "r"((A)[1]), "r"((A)[2]), "r"((A)[3]),                 \
          "r"((B)[0]), "r"((B)[1]))

__device__ __forceinline__ uint32_t h2u(__half2 h) { return *(uint32_t*)&h; }

// ---------------- init ----------------
__global__ void k_init() {
    if (threadIdx.x < NGRP)
        g_cnt[threadIdx.x] = (threadIdx.x == NEXP) ? NTOK : 0;
}

// ---------------- router: warp per token ----------------
__global__ void k_router(const float* __restrict__ x, const float* __restrict__ gw) {
    int gtid = blockIdx.x * blockDim.x + threadIdx.x;
    int t    = gtid >> 5;
    int lane = gtid & 31;
    if (t >= NTOK) return;

    const float* xr = x + (size_t)t * HDIM;
    float acc[NEXP];
#pragma unroll
    for (int e = 0; e < NEXP; e++) acc[e] = 0.f;
    for (int k = lane; k < HDIM; k += 32) {
        float xv = xr[k];
        const float4* gr = (const float4*)(gw + (size_t)k * NEXP);
        float4 g0 = gr[0], g1 = gr[1];
        acc[0] += xv * g0.x; acc[1] += xv * g0.y;
        acc[2] += xv * g0.z; acc[3] += xv * g0.w;
        acc[4] += xv * g1.x; acc[5] += xv * g1.y;
        acc[6] += xv * g1.z; acc[7] += xv * g1.w;
    }
#pragma unroll
    for (int e = 0; e < NEXP; e++) {
#pragma unroll
        for (int off = 16; off; off >>= 1)
            acc[e] += __shfl_xor_sync(0xffffffffu, acc[e], off);
    }
    if (lane == 0) {
        float m = acc[0];
#pragma unroll
        for (int e = 1; e < NEXP; e++) m = fmaxf(m, acc[e]);
        float p[NEXP];
#pragma unroll
        for (int e = 0; e < NEXP; e++) p[e] = expf(acc[e] - m);
        int i0 = 0; float b0 = p[0];
#pragma unroll
        for (int e = 1; e < NEXP; e++) if (p[e] > b0) { b0 = p[e]; i0 = e; }
        int i1 = (i0 == 0) ? 1 : 0; float b1 = p[i1];
#pragma unroll
        for (int e = 0; e < NEXP; e++)
            if (e != i0 && p[e] > b1) { b1 = p[e]; i1 = e; }
        float s = b0 + b1;
        int p0 = atomicAdd(&g_cnt[i0], 1);
        int p1 = atomicAdd(&g_cnt[i1], 1);
        g_tok[i0 * NTOK + p0] = t;
        g_tok[i1 * NTOK + p1] = t;
        g_te[2 * t + 0] = i0; g_tp[2 * t + 0] = p0; g_tw[2 * t + 0] = b0 / s;
        g_te[2 * t + 1] = i1; g_tp[2 * t + 1] = p1; g_tw[2 * t + 1] = b1 / s;
        g_tok[NEXP * NTOK + t] = t;
    }
}

// ============================================================================
// GEMM1 (fp16 mma m16n8k16): act = silu(x@Wg) * (x@Wu)
// Block 128 rows x 128 act-cols (B tile 256: cols 0-127 gate, 128-255 up).
// 8 warps, 2x4 grid, warp tile 64x64. Double-buffered smem, 1 barrier/iter.
// ============================================================================
__global__ __launch_bounds__(256, 1) void k_gemm1(const float* __restrict__ x,
                                                  const float* __restrict__ base_wgu,
                                                  const float* __restrict__ exp_wgu) {
    int g   = blockIdx.z;
    int cnt = g_cnt[g];
    int m0  = blockIdx.y * 128;
    if (m0 >= cnt) return;
    int n0  = blockIdx.x * 128;
    const float* W = (g == NEXP) ? base_wgu : (exp_wgu + (size_t)g * HDIM * TWOI);

    extern __shared__ uint32_t sm[];
    uint32_t* Abuf[2] = { sm, sm + A_BUF };
    uint32_t* Bbuf[2] = { sm + 2 * A_BUF, sm + 2 * A_BUF + B_BUF };
    __shared__ int stok[128];

    int tid = threadIdx.x, wid = tid >> 5, lane = tid & 31;
    int wm = wid & 1, wn = wid >> 1;
    int qg = lane >> 2, qq = lane & 3;

    if (tid < 128) { int r = m0 + tid; stok[tid] = g_tok[g * NTOK + ((r < cnt) ? r : cnt - 1)]; }
    __syncthreads();

    // A staging: rows (tid>>3)+32j, float4 chunk (tid&7)
    int arow0 = tid >> 3, af4 = tid & 7;
    const float* apt[4];
#pragma unroll
    for (int j = 0; j < 4; j++)
        apt[j] = x + (size_t)stok[arow0 + 32 * j] * HDIM + af4 * 4;

    // B staging: kp0=tid>>6 (+4j), col group cg=tid&63 (4 cols)
    int kp0 = tid >> 6, cg = tid & 63;
    size_t coloff = (cg < 32) ? (size_t)(n0 + cg * 4)
                              : ((size_t)IDIM + n0 + (cg - 32) * 4);
    const float* bbase = W + (size_t)(2 * kp0) * TWOI + coloff;

    float acc[4][8][4];
#pragma unroll
    for (int a = 0; a < 4; a++)
#pragma unroll
        for (int b = 0; b < 8; b++)
#pragma unroll
            for (int c = 0; c < 4; c++) acc[a][b][c] = 0.f;

    float4 ra[4], rb0[4], rb1[4];

    auto ldg_stage = [&](int kk) {
#pragma unroll
        for (int j = 0; j < 4; j++) ra[j] = *(const float4*)(apt[j] + kk);
#pragma unroll
        for (int j = 0; j < 4; j++) {
            const float* p = bbase + (size_t)(kk + 8 * j) * TWOI;
            rb0[j] = *(const float4*)(p);
            rb1[j] = *(const float4*)(p + TWOI);
        }
    };
    auto sts_stage = [&](uint32_t* Ab, uint32_t* Bb) {
#pragma unroll
        for (int j = 0; j < 4; j++) {
            int r = arow0 + 32 * j;
            Ab[r * AS_STRIDE + 2 * af4]     = h2u(__floats2half2_rn(ra[j].x, ra[j].y));
            Ab[r * AS_STRIDE + 2 * af4 + 1] = h2u(__floats2half2_rn(ra[j].z, ra[j].w));
            int kp = kp0 + 4 * j;
            Bb[(cg * 4 + 0) * BS_STRIDE + kp] = h2u(__floats2half2_rn(rb0[j].x, rb1[j].x));
            Bb[(cg * 4 + 1) * BS_STRIDE + kp] = h2u(__floats2half2_rn(rb0[j].y, rb1[j].y));
            Bb[(cg * 4 + 2) * BS_STRIDE + kp] = h2u(__floats2half2_rn(rb0[j].z, rb1[j].z));
            Bb[(cg * 4 + 3) * BS_STRIDE + kp] = h2u(__floats2half2_rn(rb0[j].w, rb1[j].w));
        }
    };

    ldg_stage(0);
    sts_stage(Abuf[0], Bbuf[0]);
    __syncthreads();

    const int NST = HDIM / 32;
    for (int s = 0; s < NST; s++) {
        if (s + 1 < NST) ldg_stage((s + 1) * 32);
        uint32_t* Ab = Abuf[s & 1];
        uint32_t* Bb = Bbuf[s & 1];
#pragma unroll
        for (int ks = 0; ks < 2; ks++) {
            int hb = ks * 8 + qq;
            uint32_t af[4][4], bf[8][2];
#pragma unroll
            for (int mt = 0; mt < 4; mt++) {
                int r = wm * 64 + mt * 16 + qg;
                af[mt][0] = Ab[r * AS_STRIDE + hb];
                af[mt][1] = Ab[(r + 8) * AS_STRIDE + hb];
                af[mt][2] = Ab[r * AS_STRIDE + hb + 4];
                af[mt][3] = Ab[(r + 8) * AS_STRIDE + hb + 4];
            }
#pragma unroll
            for (int nt = 0; nt < 8; nt++) {
                int c = (nt < 4) ? (32 * wn + 8 * nt + qg)
                                 : (128 + 32 * wn + 8 * (nt - 4) + qg);
                bf[nt][0] = Bb[c * BS_STRIDE + hb];
                bf[nt][1] = Bb[c * BS_STRIDE + hb + 4];
            }
#pragma unroll
            for (int mt = 0; mt < 4; mt++)
#pragma unroll
                for (int nt = 0; nt < 8; nt++)
                    MMA_F16(acc[mt][nt], af[mt], bf[nt]);
        }
        if (s + 1 < NST) sts_stage(Abuf[(s + 1) & 1], Bbuf[(s + 1) & 1]);
        __syncthreads();
    }

    // epilogue: SwiGLU, half2 stores (write all 128 rows; padded rows harmless)
#pragma unroll
    for (int mt = 0; mt < 4; mt++) {
        int r0 = m0 + wm * 64 + mt * 16 + qg;
#pragma unroll
        for (int nt = 0; nt < 4; nt++) {
            int c = n0 + 32 * wn + 8 * nt + 2 * qq;
            float g0 = acc[mt][nt][0], g1 = acc[mt][nt][1];
            float u0 = acc[mt][nt + 4][0], u1 = acc[mt][nt + 4][1];
            *(__half2*)&g_act[((size_t)g * NTOK + r0) * IDIM + c] =
                __floats2half2_rn(u0 * (g0 / (1.f + expf(-g0))),
                                  u1 * (g1 / (1.f + expf(-g1))));
            float g2 = acc[mt][nt][2], g3 = acc[mt][nt][3];
            float u2 = acc[mt][nt + 4][2], u3 = acc[mt][nt + 4][3];
            *(__half2*)&g_act[((size_t)g * NTOK + r0 + 8) * IDIM + c] =
                __floats2half2_rn(u2 * (g2 / (1.f + expf(-g2))),
                                  u3 * (g3 / (1.f + expf(-g3))));
        }
    }
}

// ============================================================================
// GEMM2 (fp16 mma): y = act(half) @ Wd.  Block 128x256, warp 64x64.
// ============================================================================
__global__ __launch_bounds__(256, 1) void k_gemm2(const float* __restrict__ base_wd,
                                                  const float* __restrict__ exp_wd) {
    int g   = blockIdx.z;
    int cnt = g_cnt[g];
    int m0  = blockIdx.y * 128;
    if (m0 >= cnt) return;
    int n0  = blockIdx.x * 256;
    const float* W = (g == NEXP) ? base_wd : (exp_wd + (size_t)g * IDIM * HDIM);

    extern __shared__ uint32_t sm[];
    uint32_t* Abuf[2] = { sm, sm + A_BUF };
    uint32_t* Bbuf[2] = { sm + 2 * A_BUF, sm + 2 * A_BUF + B_BUF };

    int tid = threadIdx.x, wid = tid >> 5, lane = tid & 31;
    int wm = wid & 1, wn = wid >> 1;
    int qg = lane >> 2, qq = lane & 3;

    // A staging: g_act half rows (tid>>2)+64j, 8-half chunk (tid&3)
    int arow0 = tid >> 2, ac4 = tid & 3;
    const __half* abase = g_act + ((size_t)g * NTOK + m0 + arow0) * IDIM + ac4 * 8;

    // B staging: kp0=tid>>6 (+4j), cols cg*4
    int kp0 = tid >> 6, cg = tid & 63;
    const float* bbase = W + (size_t)(2 * kp0) * HDIM + n0 + cg * 4;

    float acc[4][8][4];
#pragma unroll
    for (int a = 0; a < 4; a++)
#pragma unroll
        for (int b = 0; b < 8; b++)
#pragma unroll
            for (int c = 0; c < 4; c++) acc[a][b][c] = 0.f;

    uint4  va[2];
    float4 rb0[4], rb1[4];

    auto ldg_stage = [&](int kk) {
#pragma unroll
        for (int j = 0; j < 2; j++)
            va[j] = *(const uint4*)(abase + (size_t)j * 64 * IDIM + kk);
#pragma unroll
        for (int j = 0; j < 4; j++) {
            const float* p = bbase + (size_t)(kk + 8 * j) * HDIM;
            rb0[j] = *(const float4*)(p);
            rb1[j] = *(const float4*)(p + HDIM);
        }
    };
    auto sts_stage = [&](uint32_t* Ab, uint32_t* Bb) {
#pragma unroll
        for (int j = 0; j < 2; j++) {
            int r = arow0 + 64 * j;
            *(uint4*)&Ab[r * AS_STRIDE + ac4 * 4] = va[j];
        }
#pragma unroll
        for (int j = 0; j < 4; j++) {
            int kp = kp0 + 4 * j;
            Bb[(cg * 4 + 0) * BS_STRIDE + kp] = h2u(__floats2half2_rn(rb0[j].x, rb1[j].x));
            Bb[(cg * 4 + 1) * BS_STRIDE + kp] = h2u(__floats2half2_rn(rb0[j].y, rb1[j].y));
            Bb[(cg * 4 + 2) * BS_STRIDE + kp] = h2u(__floats2half2_rn(rb0[j].z, rb1[j].z));
            Bb[(cg * 4 + 3) * BS_STRIDE + kp] = h2u(__floats2half2_rn(rb0[j].w, rb1[j].w));
        }
    };

    ldg_stage(0);
    sts_stage(Abuf[0], Bbuf[0]);
    __syncthreads();

    const int NST = IDIM / 32;   // 88
    for (int s = 0; s < NST; s++) {
        if (s + 1 < NST) ldg_stage((s + 1) * 32);
        uint32_t* Ab = Abuf[s & 1];
        uint32_t* Bb = Bbuf[s & 1];
#pragma unroll
        for (int ks = 0; ks < 2; ks++) {
            int hb = ks * 8 + qq;
            uint32_t af[4][4], bf[8][2];
#pragma unroll
            for (int mt = 0; mt < 4; mt++) {
                int r = wm * 64 + mt * 16 + qg;
                af[mt][0] = Ab[r * AS_STRIDE + hb];
                af[mt][1] = Ab[(r + 8) * AS_STRIDE + hb];
                af[mt][2] = Ab[r * AS_STRIDE + hb + 4];
                af[mt][3] = Ab[(r + 8) * AS_STRIDE + hb + 4];
            }
#pragma unroll
            for (int nt = 0; nt < 8; nt++) {
                int c = 64 * wn + 8 * nt + qg;
                bf[nt][0] = Bb[c * BS_STRIDE + hb];
                bf[nt][1] = Bb[c * BS_STRIDE + hb + 4];
            }
#pragma unroll
            for (int mt = 0; mt < 4; mt++)
#pragma unroll
                for (int nt = 0; nt < 8; nt++)
                    MMA_F16(acc[mt][nt], af[mt], bf[nt]);
        }
        if (s + 1 < NST) sts_stage(Abuf[(s + 1) & 1], Bbuf[(s + 1) & 1]);
        __syncthreads();
    }

#pragma unroll
    for (int mt = 0; mt < 4; mt++) {
        int r0 = m0 + wm * 64 + mt * 16 + qg;
#pragma unroll
        for (int nt = 0; nt < 8; nt++) {
            int c = n0 + 64 * wn + 8 * nt + 2 * qq;
            *(float2*)&g_y[((size_t)g * NTOK + r0) * HDIM + c] =
                make_float2(acc[mt][nt][0], acc[mt][nt][1]);
            *(float2*)&g_y[((size_t)g * NTOK + r0 + 8) * HDIM + c] =
                make_float2(acc[mt][nt][2], acc[mt][nt][3]);
        }
    }
}

// ---------------- combine ----------------
__global__ void k_combine(float* __restrict__ out) {
    int idx = blockIdx.x * blockDim.x + threadIdx.x;
    int t  = idx >> 8;
    int h4 = (idx & 255) << 2;
    if (t >= NTOK) return;

    int   e0 = g_te[2 * t + 0], p0 = g_tp[2 * t + 0];
    int   e1 = g_te[2 * t + 1], p1 = g_tp[2 * t + 1];
    float w0 = g_tw[2 * t + 0], w1 = g_tw[2 * t + 1];

    float4 yb = *(const float4*)&g_y[((size_t)NEXP * NTOK + t ) * HDIM + h4];
    float4 y0 = *(const float4*)&g_y[((size_t)e0   * NTOK + p0) * HDIM + h4];
    float4 y1 = *(const float4*)&g_y[((size_t)e1   * NTOK + p1) * HDIM + h4];

    float4 o;
    o.x = yb.x + w0 * y0.x + w1 * y1.x;
    o.y = yb.y + w0 * y0.y + w1 * y1.y;
    o.z = yb.z + w0 * y0.z + w1 * y1.z;
    o.w = yb.w + w0 * y0.w + w1 * y1.w;
    *(float4*)&out[(size_t)t * HDIM + h4] = o;
}

// ---------------- launch ----------------
extern "C" void kernel_launch(void* const* d_in, const int* in_sizes, int n_in,
                              void* d_out, int out_size) {
    const float* x        = (const float*)d_in[0];
    const float* gate_w   = (const float*)d_in[1];
    const float* base_wgu = (const float*)d_in[2];
    const float* base_wd  = (const float*)d_in[3];
    const float* exp_wgu  = (const float*)d_in[4];
    const float* exp_wd   = (const float*)d_in[5];
    float* out = (float*)d_out;

    cudaFuncSetAttribute(k_gemm1, cudaFuncAttributeMaxDynamicSharedMemorySize, SMEM_BYTES);
    cudaFuncSetAttribute(k_gemm2, cudaFuncAttributeMaxDynamicSharedMemorySize, SMEM_BYTES);

    k_init<<<1, 32>>>();
    k_router<<<(NTOK * 32) / 256, 256>>>(x, gate_w);
    k_gemm1<<<dim3(IDIM / 128, NTOK / 128, NGRP), 256, SMEM_BYTES>>>(x, base_wgu, exp_wgu);
    k_gemm2<<<dim3(HDIM / 256, NTOK / 128, NGRP), 256, SMEM_BYTES>>>(base_wd, exp_wd);
    k_combine<<<(NTOK * (HDIM / 4)) / 256, 256>>>(out);
}